// round 10
// baseline (speedup 1.0000x reference)
#include <cuda_runtime.h>
#include <cuda_fp16.h>
#include <cstdint>

// ---------------------------------------------------------------------------
// Device scratch (allocation-free)
// ---------------------------------------------------------------------------
__device__ __align__(256) float g_vp[2 * 256 * 1024];  // partial v (+bias in z=0)
__device__ __align__(256) float g_sp[64 * 256];        // partial dots
__device__ int g_c1 = 0;                                // grid barrier arrivals
__device__ int g_c2 = 0;                                // finalizer completions

// ---------------------------------------------------------------------------
// Helpers
// ---------------------------------------------------------------------------
__device__ __forceinline__ uint32_t smem_u32(const void* p) {
    uint32_t a;
    asm("{ .reg .u64 t; cvta.to.shared.u64 t, %1; cvt.u32.u64 %0, t; }"
        : "=r"(a) : "l"(p));
    return a;
}

__device__ __forceinline__ void ldsm_x4(uint32_t* r, uint32_t addr) {
    asm volatile("ldmatrix.sync.aligned.m8n8.x4.shared.b16 {%0,%1,%2,%3}, [%4];"
                 : "=r"(r[0]), "=r"(r[1]), "=r"(r[2]), "=r"(r[3])
                 : "r"(addr));
}

__device__ __forceinline__ void sts128(uint32_t addr, uint4 v) {
    asm volatile("st.shared.v4.b32 [%0], {%1,%2,%3,%4};"
                 :: "r"(addr), "r"(v.x), "r"(v.y), "r"(v.z), "r"(v.w) : "memory");
}

__device__ __forceinline__ void mma16816(float* d, const uint32_t* a,
                                         uint32_t b0, uint32_t b1) {
    asm volatile(
        "mma.sync.aligned.m16n8k16.row.col.f32.f16.f16.f32 "
        "{%0,%1,%2,%3}, {%4,%5,%6,%7}, {%8,%9}, {%0,%1,%2,%3};"
        : "+f"(d[0]), "+f"(d[1]), "+f"(d[2]), "+f"(d[3])
        : "r"(a[0]), "r"(a[1]), "r"(a[2]), "r"(a[3]), "r"(b0), "r"(b1));
}

__device__ __forceinline__ uint4 pack_hi8(const float4 a0, const float4 a1) {
    __half2 h0 = __floats2half2_rn(a0.x, a0.y);
    __half2 h1 = __floats2half2_rn(a0.z, a0.w);
    __half2 h2 = __floats2half2_rn(a1.x, a1.y);
    __half2 h3 = __floats2half2_rn(a1.z, a1.w);
    uint4 u;
    u.x = *reinterpret_cast<uint32_t*>(&h0);
    u.y = *reinterpret_cast<uint32_t*>(&h1);
    u.z = *reinterpret_cast<uint32_t*>(&h2);
    u.w = *reinterpret_cast<uint32_t*>(&h3);
    return u;
}

// ---------------------------------------------------------------------------
// Fused GEMM + epilogue + grid-barrier finalization (single launch).
// CTA: 64(M) x 64(N), 4 warps of 32x32. Grid (32, 4, 2) = 256 CTAs, all
// co-resident (occ 2 by smem: 33KB/CTA). Register diet: staging is packed
// fp16 uint4 (32 regs total), finalizer is unroll-1 with minimal live state.
// ---------------------------------------------------------------------------
#define A_STAGE_B 8192
#define B_STAGE_B 8192

__global__ void __launch_bounds__(128, 2)
fused_kernel(const float* __restrict__ x32, const float* __restrict__ q,
             const float* __restrict__ bias, const float* __restrict__ W32,
             float* __restrict__ out) {
    __shared__ __align__(1024) char smemA[2 * A_STAGE_B];
    __shared__ __align__(1024) char smemB[2 * B_STAGE_B];
    __shared__ float s_sm[64];
    const uint32_t sbA = smem_u32(smemA);
    const uint32_t sbB = smem_u32(smemB);

    const int tid  = threadIdx.x;
    const int lane = tid & 31;
    const int wid  = tid >> 5;            // 0..3
    const int wy   = wid >> 1;            // warp m index (0/1)
    const int wx   = wid & 1;             // warp n index (0/1)
    const int gq   = lane >> 2;           // group id 0..7
    const int tq   = lane & 3;            // quad thread 0..3

    const int n0 = blockIdx.x * 64;       // 0..2047
    const int m0 = blockIdx.y * 64;       // 0..255
    const int z  = blockIdx.z;            // split-K half
    const int c0 = z * 8;

    // Staging: packed fp16 (converted at load time) -> 16+16 regs only.
    uint4 areg[4], breg[4];
    auto ldg_AB = [&](int c) {
        const int koff = c * 64;
        #pragma unroll
        for (int s = 0; s < 4; s++) {
            int u = tid + 128 * s;
            int r = u >> 3, j = u & 7;
            const float4* sa = reinterpret_cast<const float4*>(
                x32 + (m0 + r) * 1024 + koff + j * 8);
            const float4* sb = reinterpret_cast<const float4*>(
                W32 + (n0 + r) * 1024 + koff + j * 8);
            areg[s] = pack_hi8(sa[0], sa[1]);
            breg[s] = pack_hi8(sb[0], sb[1]);
        }
    };

    auto sts_AB = [&](int buf) {
        const uint32_t baseA = sbA + buf * A_STAGE_B;
        const uint32_t baseB = sbB + buf * B_STAGE_B;
        #pragma unroll
        for (int s = 0; s < 4; s++) {
            int u = tid + 128 * s;
            int r = u >> 3, j = u & 7;
            uint32_t swz = (uint32_t)((j ^ (r & 7)) << 4);
            sts128(baseA + r * 128 + swz, areg[s]);
            sts128(baseB + r * 128 + swz, breg[s]);
        }
    };

    float acc[2][4][4];
    #pragma unroll
    for (int mi = 0; mi < 2; mi++)
        #pragma unroll
        for (int nj = 0; nj < 4; nj++)
            #pragma unroll
            for (int e = 0; e < 4; e++)
                acc[mi][nj][e] = 0.0f;

    ldg_AB(c0 + 0);

    const int lrow = lane & 15;
    const int lcb  = lane >> 4;

    for (int i = 0; i < 8; i++) {
        const int buf = i & 1;

        sts_AB(buf);
        if (i + 1 < 8) ldg_AB(c0 + i + 1);

        __syncthreads();

        const uint32_t sa = sbA + buf * A_STAGE_B;
        const uint32_t sB = sbB + buf * B_STAGE_B;

        #pragma unroll
        for (int ks = 0; ks < 4; ks++) {
            const int j = ks * 2 + lcb;
            uint32_t a[2][4], b[2][4];
            #pragma unroll
            for (int mi = 0; mi < 2; mi++) {
                int r = wy * 32 + mi * 16 + lrow;
                ldsm_x4(a[mi], sa + r * 128 + ((j ^ (r & 7)) << 4));
            }
            #pragma unroll
            for (int nb = 0; nb < 2; nb++) {
                int r = wx * 32 + nb * 16 + lrow;
                ldsm_x4(b[nb], sB + r * 128 + ((j ^ (r & 7)) << 4));
            }
            #pragma unroll
            for (int mi = 0; mi < 2; mi++)
                #pragma unroll
                for (int nj = 0; nj < 4; nj++) {
                    const int nb = nj >> 1, sub = nj & 1;
                    mma16816(acc[mi][nj], a[mi], b[nb][sub], b[nb][sub + 2]);
                }
        }
        __syncthreads();
    }

    // ------------------------------------------------------------------
    // Epilogue: write partials. acc element (mi, nj, e):
    //   row = m0 + wy*32 + mi*16 + gq + (e>=2 ? 8 : 0)
    //   col = n0 + wx*32 + nj*8  + 2*tq + (e&1)
    // Bias added only by the z==0 half.
    // ------------------------------------------------------------------
    float2 bb[4];
    #pragma unroll
    for (int nj = 0; nj < 4; nj++) {
        if (z == 0) {
            const int col = n0 + wx * 32 + nj * 8 + 2 * tq;
            bb[nj] = *reinterpret_cast<const float2*>(bias + col);
        } else {
            bb[nj].x = 0.0f; bb[nj].y = 0.0f;
        }
    }

    if (n0 < 1024) {
        float part[4];
        #pragma unroll
        for (int mi = 0; mi < 2; mi++)
            #pragma unroll
            for (int rh = 0; rh < 2; rh++) {
                const int row = m0 + wy * 32 + mi * 16 + rh * 8 + gq;
                float s = 0.0f;
                #pragma unroll
                for (int nj = 0; nj < 4; nj++) {
                    const int col = n0 + wx * 32 + nj * 8 + 2 * tq;
                    float2 qq = *reinterpret_cast<const float2*>(q + row * 1024 + col);
                    s += (acc[mi][nj][rh * 2 + 0] + bb[nj].x) * qq.x;
                    s += (acc[mi][nj][rh * 2 + 1] + bb[nj].y) * qq.y;
                }
                part[mi * 2 + rh] = s;
            }
        #pragma unroll
        for (int sl = 0; sl < 4; sl++) {
            part[sl] += __shfl_xor_sync(0xFFFFFFFFu, part[sl], 1);
            part[sl] += __shfl_xor_sync(0xFFFFFFFFu, part[sl], 2);
        }
        if (tq == 0) {
            const int slot = z * 32 + blockIdx.x * 2 + wx;   // 0..63
            #pragma unroll
            for (int sl = 0; sl < 4; sl++) {
                const int row = m0 + wy * 32 + (sl >> 1) * 16 + (sl & 1) * 8 + gq;
                g_sp[slot * 256 + row] = part[sl];
            }
        }
    } else {
        float* vbase = g_vp + z * 256 * 1024;
        #pragma unroll
        for (int mi = 0; mi < 2; mi++)
            #pragma unroll
            for (int rh = 0; rh < 2; rh++) {
                const int row = m0 + wy * 32 + mi * 16 + rh * 8 + gq;
                #pragma unroll
                for (int nj = 0; nj < 4; nj++) {
                    const int col = (n0 - 1024) + wx * 32 + nj * 8 + 2 * tq;
                    float2 o;
                    o.x = acc[mi][nj][rh * 2 + 0] + bb[nj].x;
                    o.y = acc[mi][nj][rh * 2 + 1] + bb[nj].y;
                    *reinterpret_cast<float2*>(vbase + row * 1024 + col) = o;
                }
            }
    }

    // ------------------------------------------------------------------
    // Grid barrier (all 256 CTAs co-resident at occ 2).
    // ------------------------------------------------------------------
    __threadfence();
    __syncthreads();
    if (tid == 0) atomicAdd(&g_c1, 1);

    if (z == 0 && n0 >= 1024) {
        if (tid == 0) {
            while (atomicAdd(&g_c1, 0) < 256) __nanosleep(64);
        }
        __syncthreads();

        // s[row] for this CTA's 64 rows (fixed order -> deterministic)
        if (tid < 64) {
            const int row = m0 + tid;
            float s = 0.0f;
            #pragma unroll 1
            for (int j = 0; j < 64; j++) s += g_sp[j * 256 + row];
            s_sm[tid] = s;
        }
        __syncthreads();

        // out tile: rows m0..m0+63, cols (n0-1024)..+63 — lean, unroll 1
        const int vc0 = n0 - 1024;
        #pragma unroll 1
        for (int k2 = 0; k2 < 8; k2++) {
            const int idx = tid + 128 * k2;      // 0..1023 float4 units
            const int lr = idx >> 4, lc = idx & 15;
            const int off = (m0 + lr) * 1024 + vc0 + lc * 4;
            float4 v0 = *reinterpret_cast<const float4*>(g_vp + off);
            float4 v1 = *reinterpret_cast<const float4*>(g_vp + 256 * 1024 + off);
            const float s = s_sm[lr];
            float4 o;
            o.x = (v0.x + v1.x) * s;
            o.y = (v0.y + v1.y) * s;
            o.z = (v0.z + v1.z) * s;
            o.w = (v0.w + v1.w) * s;
            *reinterpret_cast<float4*>(out + off) = o;
        }

        // Completion + counter reset (graph-replay safe)
        __threadfence();
        __syncthreads();
        if (tid == 0) {
            atomicAdd(&g_c2, 1);
            if (blockIdx.x == 16 && blockIdx.y == 0) {
                while (atomicAdd(&g_c2, 0) < 64) __nanosleep(64);
                atomicExch(&g_c1, 0);
                atomicExch(&g_c2, 0);
            }
        }
    }
}

// ---------------------------------------------------------------------------
extern "C" void kernel_launch(void* const* d_in, const int* in_sizes, int n_in,
                              void* d_out, int out_size) {
    const float* x  = (const float*)d_in[0];   // 256x1024
    const float* q  = (const float*)d_in[1];   // 256x1024
    const float* W  = (const float*)d_in[2];   // 2048x1024
    const float* bs = (const float*)d_in[3];   // 2048
    float* out = (float*)d_out;                // 256x1024

    fused_kernel<<<dim3(32, 4, 2), 128>>>(x, q, bs, W, out);
}

// round 11
// speedup vs baseline: 1.5792x; 1.5792x over previous
#include <cuda_runtime.h>
#include <cuda_fp16.h>
#include <cstdint>

// ---------------------------------------------------------------------------
// Device scratch (allocation-free)
// ---------------------------------------------------------------------------
__device__ __align__(256) float g_sp[64 * 256];   // partial dots [slot][row]

// ---------------------------------------------------------------------------
// Helpers
// ---------------------------------------------------------------------------
__device__ __forceinline__ uint32_t smem_u32(const void* p) {
    uint32_t a;
    asm("{ .reg .u64 t; cvta.to.shared.u64 t, %1; cvt.u32.u64 %0, t; }"
        : "=r"(a) : "l"(p));
    return a;
}

__device__ __forceinline__ void ldsm_x4(uint32_t* r, uint32_t addr) {
    asm volatile("ldmatrix.sync.aligned.m8n8.x4.shared.b16 {%0,%1,%2,%3}, [%4];"
                 : "=r"(r[0]), "=r"(r[1]), "=r"(r[2]), "=r"(r[3])
                 : "r"(addr));
}

__device__ __forceinline__ void sts128(uint32_t addr, uint4 v) {
    asm volatile("st.shared.v4.b32 [%0], {%1,%2,%3,%4};"
                 :: "r"(addr), "r"(v.x), "r"(v.y), "r"(v.z), "r"(v.w) : "memory");
}

__device__ __forceinline__ void mma16816(float* d, const uint32_t* a,
                                         uint32_t b0, uint32_t b1) {
    asm volatile(
        "mma.sync.aligned.m16n8k16.row.col.f32.f16.f16.f32 "
        "{%0,%1,%2,%3}, {%4,%5,%6,%7}, {%8,%9}, {%0,%1,%2,%3};"
        : "+f"(d[0]), "+f"(d[1]), "+f"(d[2]), "+f"(d[3])
        : "r"(a[0]), "r"(a[1]), "r"(a[2]), "r"(a[3]), "r"(b0), "r"(b1));
}

__device__ __forceinline__ uint4 pack_hi8(const float4 a0, const float4 a1) {
    __half2 h0 = __floats2half2_rn(a0.x, a0.y);
    __half2 h1 = __floats2half2_rn(a0.z, a0.w);
    __half2 h2 = __floats2half2_rn(a1.x, a1.y);
    __half2 h3 = __floats2half2_rn(a1.z, a1.w);
    uint4 u;
    u.x = *reinterpret_cast<uint32_t*>(&h0);
    u.y = *reinterpret_cast<uint32_t*>(&h1);
    u.z = *reinterpret_cast<uint32_t*>(&h2);
    u.w = *reinterpret_cast<uint32_t*>(&h3);
    return u;
}

// ---------------------------------------------------------------------------
// Kernel K: k-half GEMM (cols 0..1023 of kv) + fused q-dot partials.
// Tile 32(M) x 64(N), grid (16, 8, 2), split-K 2 (8 chunks of 64 k each).
// Warps 2x2: warp tile 16(M) x 32(N).
// ---------------------------------------------------------------------------
#define KA_STAGE 4096
#define KB_STAGE 8192

__global__ void __launch_bounds__(128, 2)
kkernel(const float* __restrict__ x32, const float* __restrict__ q,
        const float* __restrict__ bias, const float* __restrict__ W32) {
    __shared__ __align__(1024) char smemA[2 * KA_STAGE];
    __shared__ __align__(1024) char smemB[2 * KB_STAGE];
    const uint32_t sbA = smem_u32(smemA);
    const uint32_t sbB = smem_u32(smemB);

    const int tid  = threadIdx.x;
    const int lane = tid & 31;
    const int wid  = tid >> 5;
    const int wy   = wid >> 1;            // m half (0/1) of 16 rows
    const int wx   = wid & 1;             // n half (0/1) of 32 cols
    const int gq   = lane >> 2;
    const int tq   = lane & 3;

    const int n0 = blockIdx.x * 64;       // 0..960 (k half)
    const int m0 = blockIdx.y * 32;       // 0..224
    const int z  = blockIdx.z;
    const int c0 = z * 8;

    uint4 areg[2], breg[4];
    auto ldg_AB = [&](int c) {
        const int koff = c * 64;
        #pragma unroll
        for (int s = 0; s < 2; s++) {
            int u = tid + 128 * s;
            int r = u >> 3, j = u & 7;
            const float4* sa = reinterpret_cast<const float4*>(
                x32 + (m0 + r) * 1024 + koff + j * 8);
            areg[s] = pack_hi8(sa[0], sa[1]);
        }
        #pragma unroll
        for (int s = 0; s < 4; s++) {
            int u = tid + 128 * s;
            int r = u >> 3, j = u & 7;
            const float4* sb = reinterpret_cast<const float4*>(
                W32 + (n0 + r) * 1024 + koff + j * 8);
            breg[s] = pack_hi8(sb[0], sb[1]);
        }
    };

    auto sts_AB = [&](int buf) {
        const uint32_t baseA = sbA + buf * KA_STAGE;
        const uint32_t baseB = sbB + buf * KB_STAGE;
        #pragma unroll
        for (int s = 0; s < 2; s++) {
            int u = tid + 128 * s;
            int r = u >> 3, j = u & 7;
            sts128(baseA + r * 128 + (uint32_t)((j ^ (r & 7)) << 4), areg[s]);
        }
        #pragma unroll
        for (int s = 0; s < 4; s++) {
            int u = tid + 128 * s;
            int r = u >> 3, j = u & 7;
            sts128(baseB + r * 128 + (uint32_t)((j ^ (r & 7)) << 4), breg[s]);
        }
    };

    float acc[4][4];
    #pragma unroll
    for (int nj = 0; nj < 4; nj++)
        #pragma unroll
        for (int e = 0; e < 4; e++)
            acc[nj][e] = 0.0f;

    ldg_AB(c0 + 0);

    const int lrow = lane & 15;
    const int lcb  = lane >> 4;

    for (int i = 0; i < 8; i++) {
        const int buf = i & 1;
        sts_AB(buf);
        if (i + 1 < 8) ldg_AB(c0 + i + 1);
        __syncthreads();

        const uint32_t sa = sbA + buf * KA_STAGE;
        const uint32_t sB = sbB + buf * KB_STAGE;

        #pragma unroll
        for (int ks = 0; ks < 4; ks++) {
            const int j = ks * 2 + lcb;
            uint32_t a[4], b[2][4];
            {
                int r = wy * 16 + lrow;
                ldsm_x4(a, sa + r * 128 + ((j ^ (r & 7)) << 4));
            }
            #pragma unroll
            for (int nb = 0; nb < 2; nb++) {
                int r = wx * 32 + nb * 16 + lrow;
                ldsm_x4(b[nb], sB + r * 128 + ((j ^ (r & 7)) << 4));
            }
            #pragma unroll
            for (int nj = 0; nj < 4; nj++) {
                const int nb = nj >> 1, sub = nj & 1;
                mma16816(acc[nj], a, b[nb][sub], b[nb][sub + 2]);
            }
        }
        __syncthreads();
    }

    // Epilogue: dot with q. acc element (nj, e):
    //   row = m0 + wy*16 + gq + (e>=2 ? 8 : 0)
    //   col = n0 + wx*32 + nj*8 + 2*tq + (e&1)
    float2 bb[4];
    #pragma unroll
    for (int nj = 0; nj < 4; nj++) {
        if (z == 0) {
            const int col = n0 + wx * 32 + nj * 8 + 2 * tq;
            bb[nj] = *reinterpret_cast<const float2*>(bias + col);
        } else {
            bb[nj].x = 0.0f; bb[nj].y = 0.0f;
        }
    }

    float part[2];
    #pragma unroll
    for (int rh = 0; rh < 2; rh++) {
        const int row = m0 + wy * 16 + rh * 8 + gq;
        float s = 0.0f;
        #pragma unroll
        for (int nj = 0; nj < 4; nj++) {
            const int col = n0 + wx * 32 + nj * 8 + 2 * tq;
            float2 qq = *reinterpret_cast<const float2*>(q + row * 1024 + col);
            s += (acc[nj][rh * 2 + 0] + bb[nj].x) * qq.x;
            s += (acc[nj][rh * 2 + 1] + bb[nj].y) * qq.y;
        }
        part[rh] = s;
    }
    #pragma unroll
    for (int rh = 0; rh < 2; rh++) {
        part[rh] += __shfl_xor_sync(0xFFFFFFFFu, part[rh], 1);
        part[rh] += __shfl_xor_sync(0xFFFFFFFFu, part[rh], 2);
    }
    if (tq == 0) {
        const int slot = z * 32 + blockIdx.x * 2 + wx;    // 0..63
        #pragma unroll
        for (int rh = 0; rh < 2; rh++) {
            const int row = m0 + wy * 16 + rh * 8 + gq;
            g_sp[slot * 256 + row] = part[rh];
        }
    }
}

// ---------------------------------------------------------------------------
// Kernel V: v-half GEMM (cols 1024..2047 of kv), full K (16 chunks), fused
// final scale: out = (acc + bias) * s[row], with s reduced from g_sp.
// Tile 32(M) x 32(N), grid (32, 8). Warps 2x2: warp tile 16 x 16.
// ---------------------------------------------------------------------------
#define V_STAGE 4096

__global__ void __launch_bounds__(128, 2)
vkernel(const float* __restrict__ x32, const float* __restrict__ bias,
        const float* __restrict__ W32, float* __restrict__ out) {
    __shared__ __align__(1024) char smemA[2 * V_STAGE];
    __shared__ __align__(1024) char smemB[2 * V_STAGE];
    __shared__ float s4[32][4];
    __shared__ float s_sm[32];
    const uint32_t sbA = smem_u32(smemA);
    const uint32_t sbB = smem_u32(smemB);

    const int tid  = threadIdx.x;
    const int lane = tid & 31;
    const int wid  = tid >> 5;
    const int wy   = wid >> 1;            // m half (0/1)
    const int wx   = wid & 1;             // n half (0/1)
    const int gq   = lane >> 2;
    const int tq   = lane & 3;

    const int nc0 = blockIdx.x * 32;      // v col 0..992
    const int m0  = blockIdx.y * 32;      // 0..224
    const int wrow0 = 1024 + nc0;         // W row base for v half

    uint4 areg[2], breg[2];
    auto ldg_AB = [&](int c) {
        const int koff = c * 64;
        #pragma unroll
        for (int s = 0; s < 2; s++) {
            int u = tid + 128 * s;
            int r = u >> 3, j = u & 7;
            const float4* sa = reinterpret_cast<const float4*>(
                x32 + (m0 + r) * 1024 + koff + j * 8);
            const float4* sb = reinterpret_cast<const float4*>(
                W32 + (wrow0 + r) * 1024 + koff + j * 8);
            areg[s] = pack_hi8(sa[0], sa[1]);
            breg[s] = pack_hi8(sb[0], sb[1]);
        }
    };

    auto sts_AB = [&](int buf) {
        const uint32_t baseA = sbA + buf * V_STAGE;
        const uint32_t baseB = sbB + buf * V_STAGE;
        #pragma unroll
        for (int s = 0; s < 2; s++) {
            int u = tid + 128 * s;
            int r = u >> 3, j = u & 7;
            uint32_t swz = (uint32_t)((j ^ (r & 7)) << 4);
            sts128(baseA + r * 128 + swz, areg[s]);
            sts128(baseB + r * 128 + swz, breg[s]);
        }
    };

    float acc[2][4];
    #pragma unroll
    for (int nj = 0; nj < 2; nj++)
        #pragma unroll
        for (int e = 0; e < 4; e++)
            acc[nj][e] = 0.0f;

    ldg_AB(0);

    const int lrow = lane & 15;
    const int lcb  = lane >> 4;

    for (int i = 0; i < 16; i++) {
        const int buf = i & 1;
        sts_AB(buf);
        if (i + 1 < 16) ldg_AB(i + 1);
        __syncthreads();

        const uint32_t sa = sbA + buf * V_STAGE;
        const uint32_t sB = sbB + buf * V_STAGE;

        #pragma unroll
        for (int ks = 0; ks < 4; ks++) {
            const int j = ks * 2 + lcb;
            uint32_t a[4], b[4];
            {
                int r = wy * 16 + lrow;
                ldsm_x4(a, sa + r * 128 + ((j ^ (r & 7)) << 4));
            }
            {
                int r = wx * 16 + lrow;
                ldsm_x4(b, sB + r * 128 + ((j ^ (r & 7)) << 4));
            }
            mma16816(acc[0], a, b[0], b[2]);
            mma16816(acc[1], a, b[1], b[3]);
        }
        __syncthreads();
    }

    // ------------------------------------------------------------------
    // s[row] for rows m0..m0+31: fixed-order reduction of 64 slots.
    // Thread t: row t>>2, quarter t&3 sums 16 slots; then 4-way combine.
    // ------------------------------------------------------------------
    {
        const int rl = tid >> 2;          // 0..31
        const int qr = tid & 3;
        float s = 0.0f;
        #pragma unroll
        for (int j2 = 0; j2 < 16; j2++)
            s += g_sp[(qr * 16 + j2) * 256 + m0 + rl];
        s4[rl][qr] = s;
    }
    __syncthreads();
    if (tid < 32)
        s_sm[tid] = (s4[tid][0] + s4[tid][1]) + (s4[tid][2] + s4[tid][3]);
    __syncthreads();

    // ------------------------------------------------------------------
    // Output: acc element (nj, e):
    //   row = m0 + wy*16 + gq + (e>=2 ? 8 : 0)
    //   col = nc0 + wx*16 + nj*8 + 2*tq + (e&1)
    // out = (acc + bias[1024+col]) * s[row]
    // ------------------------------------------------------------------
    #pragma unroll
    for (int nj = 0; nj < 2; nj++) {
        const int col = nc0 + wx * 16 + nj * 8 + 2 * tq;
        float2 bb = *reinterpret_cast<const float2*>(bias + 1024 + col);
        #pragma unroll
        for (int rh = 0; rh < 2; rh++) {
            const int row = m0 + wy * 16 + rh * 8 + gq;
            const float s = s_sm[row - m0];
            float2 o;
            o.x = (acc[nj][rh * 2 + 0] + bb.x) * s;
            o.y = (acc[nj][rh * 2 + 1] + bb.y) * s;
            *reinterpret_cast<float2*>(out + row * 1024 + col) = o;
        }
    }
}

// ---------------------------------------------------------------------------
extern "C" void kernel_launch(void* const* d_in, const int* in_sizes, int n_in,
                              void* d_out, int out_size) {
    const float* x  = (const float*)d_in[0];   // 256x1024
    const float* q  = (const float*)d_in[1];   // 256x1024
    const float* W  = (const float*)d_in[2];   // 2048x1024
    const float* bs = (const float*)d_in[3];   // 2048
    float* out = (float*)d_out;                // 256x1024

    kkernel<<<dim3(16, 8, 2), 128>>>(x, q, bs, W);
    vkernel<<<dim3(32, 8), 128>>>(x, bs, W, out);
}

// round 12
// speedup vs baseline: 1.6983x; 1.0754x over previous
#include <cuda_runtime.h>
#include <cuda_fp16.h>
#include <cstdint>

// ---------------------------------------------------------------------------
// Device scratch (allocation-free)
// ---------------------------------------------------------------------------
__device__ __align__(256) float g_sp[64 * 256];   // partial dots [slot][row]

// ---------------------------------------------------------------------------
// Helpers
// ---------------------------------------------------------------------------
__device__ __forceinline__ uint32_t smem_u32(const void* p) {
    uint32_t a;
    asm("{ .reg .u64 t; cvta.to.shared.u64 t, %1; cvt.u32.u64 %0, t; }"
        : "=r"(a) : "l"(p));
    return a;
}

__device__ __forceinline__ void ldsm_x4(uint32_t* r, uint32_t addr) {
    asm volatile("ldmatrix.sync.aligned.m8n8.x4.shared.b16 {%0,%1,%2,%3}, [%4];"
                 : "=r"(r[0]), "=r"(r[1]), "=r"(r[2]), "=r"(r[3])
                 : "r"(addr));
}

__device__ __forceinline__ void sts128(uint32_t addr, uint4 v) {
    asm volatile("st.shared.v4.b32 [%0], {%1,%2,%3,%4};"
                 :: "r"(addr), "r"(v.x), "r"(v.y), "r"(v.z), "r"(v.w) : "memory");
}

__device__ __forceinline__ void mma16816(float* d, const uint32_t* a,
                                         uint32_t b0, uint32_t b1) {
    asm volatile(
        "mma.sync.aligned.m16n8k16.row.col.f32.f16.f16.f32 "
        "{%0,%1,%2,%3}, {%4,%5,%6,%7}, {%8,%9}, {%0,%1,%2,%3};"
        : "+f"(d[0]), "+f"(d[1]), "+f"(d[2]), "+f"(d[3])
        : "r"(a[0]), "r"(a[1]), "r"(a[2]), "r"(a[3]), "r"(b0), "r"(b1));
}

__device__ __forceinline__ uint4 pack_hi8(const float4 a0, const float4 a1) {
    __half2 h0 = __floats2half2_rn(a0.x, a0.y);
    __half2 h1 = __floats2half2_rn(a0.z, a0.w);
    __half2 h2 = __floats2half2_rn(a1.x, a1.y);
    __half2 h3 = __floats2half2_rn(a1.z, a1.w);
    uint4 u;
    u.x = *reinterpret_cast<uint32_t*>(&h0);
    u.y = *reinterpret_cast<uint32_t*>(&h1);
    u.z = *reinterpret_cast<uint32_t*>(&h2);
    u.w = *reinterpret_cast<uint32_t*>(&h3);
    return u;
}

// ---------------------------------------------------------------------------
// Kernel K: k-half GEMM (cols 0..1023 of kv) + fused q-dot partials.
// Also zeroes `out` (V kernel atomically accumulates into it afterwards).
// Tile 32(M) x 64(N), grid (16, 8, 2), split-K 2 (8 chunks of 64 k each).
// ---------------------------------------------------------------------------
#define KA_STAGE 4096
#define KB_STAGE 8192

__global__ void __launch_bounds__(128, 2)
kkernel(const float* __restrict__ x32, const float* __restrict__ q,
        const float* __restrict__ bias, const float* __restrict__ W32,
        float* __restrict__ out) {
    __shared__ __align__(1024) char smemA[2 * KA_STAGE];
    __shared__ __align__(1024) char smemB[2 * KB_STAGE];
    const uint32_t sbA = smem_u32(smemA);
    const uint32_t sbB = smem_u32(smemB);

    const int tid  = threadIdx.x;
    const int lane = tid & 31;
    const int wid  = tid >> 5;
    const int wy   = wid >> 1;            // m half (0/1) of 16 rows
    const int wx   = wid & 1;             // n half (0/1) of 32 cols
    const int gq   = lane >> 2;
    const int tq   = lane & 3;

    const int n0 = blockIdx.x * 64;       // 0..960 (k half)
    const int m0 = blockIdx.y * 32;       // 0..224
    const int z  = blockIdx.z;
    const int c0 = z * 8;

    // Zero this CTA's 1024-float slice of out (V adds into it later).
    {
        const int cta = blockIdx.x + 16 * blockIdx.y + 128 * z;   // 0..255
        float4* o4 = reinterpret_cast<float4*>(out + cta * 1024);
        const float4 zz = make_float4(0.f, 0.f, 0.f, 0.f);
        o4[tid]       = zz;
        o4[tid + 128] = zz;
    }

    uint4 areg[2], breg[4];
    auto ldg_AB = [&](int c) {
        const int koff = c * 64;
        #pragma unroll
        for (int s = 0; s < 2; s++) {
            int u = tid + 128 * s;
            int r = u >> 3, j = u & 7;
            const float4* sa = reinterpret_cast<const float4*>(
                x32 + (m0 + r) * 1024 + koff + j * 8);
            areg[s] = pack_hi8(sa[0], sa[1]);
        }
        #pragma unroll
        for (int s = 0; s < 4; s++) {
            int u = tid + 128 * s;
            int r = u >> 3, j = u & 7;
            const float4* sb = reinterpret_cast<const float4*>(
                W32 + (n0 + r) * 1024 + koff + j * 8);
            breg[s] = pack_hi8(sb[0], sb[1]);
        }
    };

    auto sts_AB = [&](int buf) {
        const uint32_t baseA = sbA + buf * KA_STAGE;
        const uint32_t baseB = sbB + buf * KB_STAGE;
        #pragma unroll
        for (int s = 0; s < 2; s++) {
            int u = tid + 128 * s;
            int r = u >> 3, j = u & 7;
            sts128(baseA + r * 128 + (uint32_t)((j ^ (r & 7)) << 4), areg[s]);
        }
        #pragma unroll
        for (int s = 0; s < 4; s++) {
            int u = tid + 128 * s;
            int r = u >> 3, j = u & 7;
            sts128(baseB + r * 128 + (uint32_t)((j ^ (r & 7)) << 4), breg[s]);
        }
    };

    float acc[4][4];
    #pragma unroll
    for (int nj = 0; nj < 4; nj++)
        #pragma unroll
        for (int e = 0; e < 4; e++)
            acc[nj][e] = 0.0f;

    ldg_AB(c0 + 0);

    const int lrow = lane & 15;
    const int lcb  = lane >> 4;

    for (int i = 0; i < 8; i++) {
        const int buf = i & 1;
        sts_AB(buf);
        if (i + 1 < 8) ldg_AB(c0 + i + 1);
        __syncthreads();

        const uint32_t sa = sbA + buf * KA_STAGE;
        const uint32_t sB = sbB + buf * KB_STAGE;

        #pragma unroll
        for (int ks = 0; ks < 4; ks++) {
            const int j = ks * 2 + lcb;
            uint32_t a[4], b[2][4];
            {
                int r = wy * 16 + lrow;
                ldsm_x4(a, sa + r * 128 + ((j ^ (r & 7)) << 4));
            }
            #pragma unroll
            for (int nb = 0; nb < 2; nb++) {
                int r = wx * 32 + nb * 16 + lrow;
                ldsm_x4(b[nb], sB + r * 128 + ((j ^ (r & 7)) << 4));
            }
            #pragma unroll
            for (int nj = 0; nj < 4; nj++) {
                const int nb = nj >> 1, sub = nj & 1;
                mma16816(acc[nj], a, b[nb][sub], b[nb][sub + 2]);
            }
        }
        __syncthreads();
    }

    // Epilogue: dot with q -> partial slots.
    float2 bb[4];
    #pragma unroll
    for (int nj = 0; nj < 4; nj++) {
        if (z == 0) {
            const int col = n0 + wx * 32 + nj * 8 + 2 * tq;
            bb[nj] = *reinterpret_cast<const float2*>(bias + col);
        } else {
            bb[nj].x = 0.0f; bb[nj].y = 0.0f;
        }
    }

    float part[2];
    #pragma unroll
    for (int rh = 0; rh < 2; rh++) {
        const int row = m0 + wy * 16 + rh * 8 + gq;
        float s = 0.0f;
        #pragma unroll
        for (int nj = 0; nj < 4; nj++) {
            const int col = n0 + wx * 32 + nj * 8 + 2 * tq;
            float2 qq = *reinterpret_cast<const float2*>(q + row * 1024 + col);
            s += (acc[nj][rh * 2 + 0] + bb[nj].x) * qq.x;
            s += (acc[nj][rh * 2 + 1] + bb[nj].y) * qq.y;
        }
        part[rh] = s;
    }
    #pragma unroll
    for (int rh = 0; rh < 2; rh++) {
        part[rh] += __shfl_xor_sync(0xFFFFFFFFu, part[rh], 1);
        part[rh] += __shfl_xor_sync(0xFFFFFFFFu, part[rh], 2);
    }
    if (tq == 0) {
        const int slot = z * 32 + blockIdx.x * 2 + wx;    // 0..63
        #pragma unroll
        for (int rh = 0; rh < 2; rh++) {
            const int row = m0 + wy * 16 + rh * 8 + gq;
            g_sp[slot * 256 + row] = part[rh];
        }
    }
}

// ---------------------------------------------------------------------------
// Kernel V: v-half GEMM, SAME shape as kkernel (32x64 tiles, split-K 2,
// grid (16,8,2) = 256 CTAs). Epilogue: s[row] from g_sp (fixed order), then
// atomicAdd (acc + bias_{z=0}) * s into out. Exactly 2 atomic contributions
// per element -> bit-deterministic (fp add of two values is commutative).
// ---------------------------------------------------------------------------
__global__ void __launch_bounds__(128, 2)
vkernel(const float* __restrict__ x32, const float* __restrict__ bias,
        const float* __restrict__ W32, float* __restrict__ out) {
    __shared__ __align__(1024) char smemA[2 * KA_STAGE];
    __shared__ __align__(1024) char smemB[2 * KB_STAGE];
    __shared__ float s4[32][4];
    __shared__ float s_sm[32];
    const uint32_t sbA = smem_u32(smemA);
    const uint32_t sbB = smem_u32(smemB);

    const int tid  = threadIdx.x;
    const int lane = tid & 31;
    const int wid  = tid >> 5;
    const int wy   = wid >> 1;
    const int wx   = wid & 1;
    const int gq   = lane >> 2;
    const int tq   = lane & 3;

    const int n0v = blockIdx.x * 64;      // 0..960 within v half
    const int m0  = blockIdx.y * 32;      // 0..224
    const int z   = blockIdx.z;
    const int c0  = z * 8;
    const int wrow0 = 1024 + n0v;         // W row base for v half

    uint4 areg[2], breg[4];
    auto ldg_AB = [&](int c) {
        const int koff = c * 64;
        #pragma unroll
        for (int s = 0; s < 2; s++) {
            int u = tid + 128 * s;
            int r = u >> 3, j = u & 7;
            const float4* sa = reinterpret_cast<const float4*>(
                x32 + (m0 + r) * 1024 + koff + j * 8);
            areg[s] = pack_hi8(sa[0], sa[1]);
        }
        #pragma unroll
        for (int s = 0; s < 4; s++) {
            int u = tid + 128 * s;
            int r = u >> 3, j = u & 7;
            const float4* sb = reinterpret_cast<const float4*>(
                W32 + (wrow0 + r) * 1024 + koff + j * 8);
            breg[s] = pack_hi8(sb[0], sb[1]);
        }
    };

    auto sts_AB = [&](int buf) {
        const uint32_t baseA = sbA + buf * KA_STAGE;
        const uint32_t baseB = sbB + buf * KB_STAGE;
        #pragma unroll
        for (int s = 0; s < 2; s++) {
            int u = tid + 128 * s;
            int r = u >> 3, j = u & 7;
            sts128(baseA + r * 128 + (uint32_t)((j ^ (r & 7)) << 4), areg[s]);
        }
        #pragma unroll
        for (int s = 0; s < 4; s++) {
            int u = tid + 128 * s;
            int r = u >> 3, j = u & 7;
            sts128(baseB + r * 128 + (uint32_t)((j ^ (r & 7)) << 4), breg[s]);
        }
    };

    float acc[4][4];
    #pragma unroll
    for (int nj = 0; nj < 4; nj++)
        #pragma unroll
        for (int e = 0; e < 4; e++)
            acc[nj][e] = 0.0f;

    ldg_AB(c0 + 0);

    const int lrow = lane & 15;
    const int lcb  = lane >> 4;

    for (int i = 0; i < 8; i++) {
        const int buf = i & 1;
        sts_AB(buf);
        if (i + 1 < 8) ldg_AB(c0 + i + 1);
        __syncthreads();

        const uint32_t sa = sbA + buf * KA_STAGE;
        const uint32_t sB = sbB + buf * KB_STAGE;

        #pragma unroll
        for (int ks = 0; ks < 4; ks++) {
            const int j = ks * 2 + lcb;
            uint32_t a[4], b[2][4];
            {
                int r = wy * 16 + lrow;
                ldsm_x4(a, sa + r * 128 + ((j ^ (r & 7)) << 4));
            }
            #pragma unroll
            for (int nb = 0; nb < 2; nb++) {
                int r = wx * 32 + nb * 16 + lrow;
                ldsm_x4(b[nb], sB + r * 128 + ((j ^ (r & 7)) << 4));
            }
            #pragma unroll
            for (int nj = 0; nj < 4; nj++) {
                const int nb = nj >> 1, sub = nj & 1;
                mma16816(acc[nj], a, b[nb][sub], b[nb][sub + 2]);
            }
        }
        __syncthreads();
    }

    // s[row] for rows m0..m0+31: fixed-order reduction of 64 slots.
    {
        const int rl = tid >> 2;          // 0..31
        const int qr = tid & 3;
        float s = 0.0f;
        #pragma unroll
        for (int j2 = 0; j2 < 16; j2++)
            s += g_sp[(qr * 16 + j2) * 256 + m0 + rl];
        s4[rl][qr] = s;
    }
    __syncthreads();
    if (tid < 32)
        s_sm[tid] = (s4[tid][0] + s4[tid][1]) + (s4[tid][2] + s4[tid][3]);
    __syncthreads();

    // Epilogue: atomicAdd (acc + bias_{z=0}) * s[row] into out.
    #pragma unroll
    for (int nj = 0; nj < 4; nj++) {
        const int col = n0v + wx * 32 + nj * 8 + 2 * tq;
        float2 bb;
        if (z == 0) bb = *reinterpret_cast<const float2*>(bias + 1024 + col);
        else { bb.x = 0.0f; bb.y = 0.0f; }
        #pragma unroll
        for (int rh = 0; rh < 2; rh++) {
            const int row = m0 + wy * 16 + rh * 8 + gq;
            const float s = s_sm[row - m0];
            atomicAdd(out + row * 1024 + col,     (acc[nj][rh * 2 + 0] + bb.x) * s);
            atomicAdd(out + row * 1024 + col + 1, (acc[nj][rh * 2 + 1] + bb.y) * s);
        }
    }
}

// ---------------------------------------------------------------------------
extern "C" void kernel_launch(void* const* d_in, const int* in_sizes, int n_in,
                              void* d_out, int out_size) {
    const float* x  = (const float*)d_in[0];   // 256x1024
    const float* q  = (const float*)d_in[1];   // 256x1024
    const float* W  = (const float*)d_in[2];   // 2048x1024
    const float* bs = (const float*)d_in[3];   // 2048
    float* out = (float*)d_out;                // 256x1024

    kkernel<<<dim3(16, 8, 2), 128>>>(x, q, bs, W, out);
    vkernel<<<dim3(16, 8, 2), 128>>>(x, bs, W, out);
}

// round 13
// speedup vs baseline: 2.1296x; 1.2539x over previous
#include <cuda_runtime.h>
#include <cuda_fp16.h>
#include <cstdint>

// ---------------------------------------------------------------------------
// Device scratch (allocation-free)
// ---------------------------------------------------------------------------
__device__ __align__(256) float g_vp[2 * 256 * 1024];  // partial v (+bias in z=0)
__device__ __align__(256) float g_sp[256 * 64];        // partial dots [row][slot]

// ---------------------------------------------------------------------------
// Helpers
// ---------------------------------------------------------------------------
__device__ __forceinline__ uint32_t smem_u32(const void* p) {
    uint32_t a;
    asm("{ .reg .u64 t; cvta.to.shared.u64 t, %1; cvt.u32.u64 %0, t; }"
        : "=r"(a) : "l"(p));
    return a;
}

__device__ __forceinline__ void ldsm_x4(uint32_t* r, uint32_t addr) {
    asm volatile("ldmatrix.sync.aligned.m8n8.x4.shared.b16 {%0,%1,%2,%3}, [%4];"
                 : "=r"(r[0]), "=r"(r[1]), "=r"(r[2]), "=r"(r[3])
                 : "r"(addr));
}

__device__ __forceinline__ void sts128(uint32_t addr, uint4 v) {
    asm volatile("st.shared.v4.b32 [%0], {%1,%2,%3,%4};"
                 :: "r"(addr), "r"(v.x), "r"(v.y), "r"(v.z), "r"(v.w) : "memory");
}

__device__ __forceinline__ void mma16816(float* d, const uint32_t* a,
                                         uint32_t b0, uint32_t b1) {
    asm volatile(
        "mma.sync.aligned.m16n8k16.row.col.f32.f16.f16.f32 "
        "{%0,%1,%2,%3}, {%4,%5,%6,%7}, {%8,%9}, {%0,%1,%2,%3};"
        : "+f"(d[0]), "+f"(d[1]), "+f"(d[2]), "+f"(d[3])
        : "r"(a[0]), "r"(a[1]), "r"(a[2]), "r"(a[3]), "r"(b0), "r"(b1));
}

__device__ __forceinline__ uint4 pack_hi8(const float4 a0, const float4 a1) {
    __half2 h0 = __floats2half2_rn(a0.x, a0.y);
    __half2 h1 = __floats2half2_rn(a0.z, a0.w);
    __half2 h2 = __floats2half2_rn(a1.x, a1.y);
    __half2 h3 = __floats2half2_rn(a1.z, a1.w);
    uint4 u;
    u.x = *reinterpret_cast<uint32_t*>(&h0);
    u.y = *reinterpret_cast<uint32_t*>(&h1);
    u.z = *reinterpret_cast<uint32_t*>(&h2);
    u.w = *reinterpret_cast<uint32_t*>(&h3);
    return u;
}

// ---------------------------------------------------------------------------
// GEMM: both A (x) and B (W) loaded fp32 from global, packed to fp16 at load,
// STS to double-buffered smem. ONE __syncthreads per k-chunk:
//   iter i: sts(chunk i+1 -> buf (i+1)&1); ldg(chunk i+2); mma(buf i&1); sync
// (the sts target is never the buffer being read this iteration).
// CTA: 64(M) x 64(N), 4 warps of 32x32. Grid (32, 4, 2), split-K 2.
// ---------------------------------------------------------------------------
#define A_STAGE_B 8192
#define B_STAGE_B 8192

__global__ void __launch_bounds__(128, 2)
gemm_kernel(const float* __restrict__ x32, const float* __restrict__ q,
            const float* __restrict__ bias, const float* __restrict__ W32) {
    __shared__ __align__(1024) char smemA[2 * A_STAGE_B];
    __shared__ __align__(1024) char smemB[2 * B_STAGE_B];
    const uint32_t sbA = smem_u32(smemA);
    const uint32_t sbB = smem_u32(smemB);

    const int tid  = threadIdx.x;
    const int lane = tid & 31;
    const int wid  = tid >> 5;            // 0..3
    const int wy   = wid >> 1;            // warp m index (0/1)
    const int wx   = wid & 1;             // warp n index (0/1)
    const int gq   = lane >> 2;           // group id 0..7
    const int tq   = lane & 3;            // quad thread 0..3

    const int n0 = blockIdx.x * 64;       // 0..2047
    const int m0 = blockIdx.y * 64;       // 0..255
    const int z  = blockIdx.z;            // split-K half
    const int c0 = z * 8;

    // Staging: packed fp16 (converted at load) -> 16+16 regs.
    uint4 areg[4], breg[4];
    auto ldg_AB = [&](int c) {
        const int koff = c * 64;
        #pragma unroll
        for (int s = 0; s < 4; s++) {
            int u = tid + 128 * s;
            int r = u >> 3, j = u & 7;
            const float4* sa = reinterpret_cast<const float4*>(
                x32 + (m0 + r) * 1024 + koff + j * 8);
            const float4* sb = reinterpret_cast<const float4*>(
                W32 + (n0 + r) * 1024 + koff + j * 8);
            areg[s] = pack_hi8(sa[0], sa[1]);
            breg[s] = pack_hi8(sb[0], sb[1]);
        }
    };

    auto sts_AB = [&](int buf) {
        const uint32_t baseA = sbA + buf * A_STAGE_B;
        const uint32_t baseB = sbB + buf * B_STAGE_B;
        #pragma unroll
        for (int s = 0; s < 4; s++) {
            int u = tid + 128 * s;
            int r = u >> 3, j = u & 7;
            uint32_t swz = (uint32_t)((j ^ (r & 7)) << 4);
            sts128(baseA + r * 128 + swz, areg[s]);
            sts128(baseB + r * 128 + swz, breg[s]);
        }
    };

    float acc[2][4][4];
    #pragma unroll
    for (int mi = 0; mi < 2; mi++)
        #pragma unroll
        for (int nj = 0; nj < 4; nj++)
            #pragma unroll
            for (int e = 0; e < 4; e++)
                acc[mi][nj][e] = 0.0f;

    // Prologue: chunk0 -> buf0; chunk1 -> regs; one sync.
    ldg_AB(c0 + 0);
    sts_AB(0);
    ldg_AB(c0 + 1);
    __syncthreads();

    const int lrow = lane & 15;
    const int lcb  = lane >> 4;

    for (int i = 0; i < 8; i++) {
        const int buf = i & 1;

        if (i + 1 < 8) sts_AB((i + 1) & 1);   // regs(chunk i+1) -> other buffer
        if (i + 2 < 8) ldg_AB(c0 + i + 2);    // prefetch chunk i+2 into regs

        const uint32_t sa = sbA + buf * A_STAGE_B;
        const uint32_t sB = sbB + buf * B_STAGE_B;

        #pragma unroll
        for (int ks = 0; ks < 4; ks++) {
            const int j = ks * 2 + lcb;
            uint32_t a[2][4], b[2][4];
            #pragma unroll
            for (int mi = 0; mi < 2; mi++) {
                int r = wy * 32 + mi * 16 + lrow;
                ldsm_x4(a[mi], sa + r * 128 + ((j ^ (r & 7)) << 4));
            }
            #pragma unroll
            for (int nb = 0; nb < 2; nb++) {
                int r = wx * 32 + nb * 16 + lrow;
                ldsm_x4(b[nb], sB + r * 128 + ((j ^ (r & 7)) << 4));
            }
            #pragma unroll
            for (int mi = 0; mi < 2; mi++)
                #pragma unroll
                for (int nj = 0; nj < 4; nj++) {
                    const int nb = nj >> 1, sub = nj & 1;
                    mma16816(acc[mi][nj], a[mi], b[nb][sub], b[nb][sub + 2]);
                }
        }
        __syncthreads();   // sts(i+1) visible; buf free for overwrite next iter
    }

    // ------------------------------------------------------------------
    // Fused epilogue. acc element (mi, nj, e):
    //   row = m0 + wy*32 + mi*16 + gq + (e>=2 ? 8 : 0)
    //   col = n0 + wx*32 + nj*8  + 2*tq + (e&1)
    // Bias added only by the z==0 half.
    // ------------------------------------------------------------------
    float2 bb[4];
    #pragma unroll
    for (int nj = 0; nj < 4; nj++) {
        if (z == 0) {
            const int col = n0 + wx * 32 + nj * 8 + 2 * tq;
            bb[nj] = *reinterpret_cast<const float2*>(bias + col);
        } else {
            bb[nj].x = 0.0f; bb[nj].y = 0.0f;
        }
    }

    if (n0 < 1024) {
        float part[4];
        #pragma unroll
        for (int mi = 0; mi < 2; mi++)
            #pragma unroll
            for (int rh = 0; rh < 2; rh++) {
                const int row = m0 + wy * 32 + mi * 16 + rh * 8 + gq;
                float s = 0.0f;
                #pragma unroll
                for (int nj = 0; nj < 4; nj++) {
                    const int col = n0 + wx * 32 + nj * 8 + 2 * tq;
                    float2 qq = *reinterpret_cast<const float2*>(q + row * 1024 + col);
                    s += (acc[mi][nj][rh * 2 + 0] + bb[nj].x) * qq.x;
                    s += (acc[mi][nj][rh * 2 + 1] + bb[nj].y) * qq.y;
                }
                part[mi * 2 + rh] = s;
            }
        #pragma unroll
        for (int sl = 0; sl < 4; sl++) {
            part[sl] += __shfl_xor_sync(0xFFFFFFFFu, part[sl], 1);
            part[sl] += __shfl_xor_sync(0xFFFFFFFFu, part[sl], 2);
        }
        if (tq == 0) {
            const int slot = z * 32 + blockIdx.x * 2 + wx;   // 0..63
            #pragma unroll
            for (int sl = 0; sl < 4; sl++) {
                const int row = m0 + wy * 32 + (sl >> 1) * 16 + (sl & 1) * 8 + gq;
                g_sp[row * 64 + slot] = part[sl];
            }
        }
    } else {
        float* vbase = g_vp + z * 256 * 1024;
        #pragma unroll
        for (int mi = 0; mi < 2; mi++)
            #pragma unroll
            for (int rh = 0; rh < 2; rh++) {
                const int row = m0 + wy * 32 + mi * 16 + rh * 8 + gq;
                #pragma unroll
                for (int nj = 0; nj < 4; nj++) {
                    const int col = (n0 - 1024) + wx * 32 + nj * 8 + 2 * tq;
                    float2 o;
                    o.x = acc[mi][nj][rh * 2 + 0] + bb[nj].x;
                    o.y = acc[mi][nj][rh * 2 + 1] + bb[nj].y;
                    *reinterpret_cast<float2*>(vbase + row * 1024 + col) = o;
                }
            }
    }
}

// ---------------------------------------------------------------------------
// Scale: out[b,:] = (v0[b,:]+v1[b,:]) * sum(g_sp[b][0..63])
// g_sp row-major -> the 64-slot read is one coalesced line-set per block.
// ---------------------------------------------------------------------------
__global__ __launch_bounds__(256) void scale_kernel(float* __restrict__ out) {
    const int b = blockIdx.x;
    const int t = threadIdx.x;
    const int w = t >> 5, l = t & 31;

    __shared__ float red[2];
    __shared__ float s_tot;
    float p = (t < 64) ? g_sp[b * 64 + t] : 0.0f;
    #pragma unroll
    for (int off = 16; off > 0; off >>= 1)
        p += __shfl_xor_sync(0xFFFFFFFFu, p, off);
    if (w < 2 && l == 0) red[w] = p;
    __syncthreads();
    if (t == 0) s_tot = red[0] + red[1];
    __syncthreads();
    const float s = s_tot;

    float4 v0 = reinterpret_cast<const float4*>(g_vp + b * 1024)[t];
    float4 v1 = reinterpret_cast<const float4*>(g_vp + 256 * 1024 + b * 1024)[t];
    float4 o;
    o.x = (v0.x + v1.x) * s;
    o.y = (v0.y + v1.y) * s;
    o.z = (v0.z + v1.z) * s;
    o.w = (v0.w + v1.w) * s;
    reinterpret_cast<float4*>(out + b * 1024)[t] = o;
}

// ---------------------------------------------------------------------------
extern "C" void kernel_launch(void* const* d_in, const int* in_sizes, int n_in,
                              void* d_out, int out_size) {
    const float* x  = (const float*)d_in[0];   // 256x1024
    const float* q  = (const float*)d_in[1];   // 256x1024
    const float* W  = (const float*)d_in[2];   // 2048x1024
    const float* bs = (const float*)d_in[3];   // 2048
    float* out = (float*)d_out;                // 256x1024

    gemm_kernel<<<dim3(32, 4, 2), 128>>>(x, q, bs, W);
    scale_kernel<<<256, 256>>>(out);
}

// round 14
// speedup vs baseline: 2.3704x; 1.1131x over previous
#include <cuda_runtime.h>
#include <cuda_fp16.h>
#include <cstdint>

// ---------------------------------------------------------------------------
// Device scratch (allocation-free)
// ---------------------------------------------------------------------------
__device__ __align__(256) float g_vp[2 * 256 * 1024];  // partial v (+bias in z=0)
__device__ __align__(256) float g_sp[256 * 64];        // partial dots [row][slot]

// ---------------------------------------------------------------------------
// Helpers
// ---------------------------------------------------------------------------
__device__ __forceinline__ uint32_t smem_u32(const void* p) {
    uint32_t a;
    asm("{ .reg .u64 t; cvta.to.shared.u64 t, %1; cvt.u32.u64 %0, t; }"
        : "=r"(a) : "l"(p));
    return a;
}

__device__ __forceinline__ void ldsm_x4(uint32_t* r, uint32_t addr) {
    asm volatile("ldmatrix.sync.aligned.m8n8.x4.shared.b16 {%0,%1,%2,%3}, [%4];"
                 : "=r"(r[0]), "=r"(r[1]), "=r"(r[2]), "=r"(r[3])
                 : "r"(addr));
}

__device__ __forceinline__ void sts128(uint32_t addr, uint4 v) {
    asm volatile("st.shared.v4.b32 [%0], {%1,%2,%3,%4};"
                 :: "r"(addr), "r"(v.x), "r"(v.y), "r"(v.z), "r"(v.w) : "memory");
}

__device__ __forceinline__ void mma16816(float* d, const uint32_t* a,
                                         uint32_t b0, uint32_t b1) {
    asm volatile(
        "mma.sync.aligned.m16n8k16.row.col.f32.f16.f16.f32 "
        "{%0,%1,%2,%3}, {%4,%5,%6,%7}, {%8,%9}, {%0,%1,%2,%3};"
        : "+f"(d[0]), "+f"(d[1]), "+f"(d[2]), "+f"(d[3])
        : "r"(a[0]), "r"(a[1]), "r"(a[2]), "r"(a[3]), "r"(b0), "r"(b1));
}

__device__ __forceinline__ uint4 pack_hi8(const float4 a0, const float4 a1) {
    __half2 h0 = __floats2half2_rn(a0.x, a0.y);
    __half2 h1 = __floats2half2_rn(a0.z, a0.w);
    __half2 h2 = __floats2half2_rn(a1.x, a1.y);
    __half2 h3 = __floats2half2_rn(a1.z, a1.w);
    uint4 u;
    u.x = *reinterpret_cast<uint32_t*>(&h0);
    u.y = *reinterpret_cast<uint32_t*>(&h1);
    u.z = *reinterpret_cast<uint32_t*>(&h2);
    u.w = *reinterpret_cast<uint32_t*>(&h3);
    return u;
}

// ---------------------------------------------------------------------------
// GEMM: A (x) and B (W) loaded fp32 into RAW float4 staging regs (no cvt on
// the load path); conversion happens at STS time (pack_hi8 inside sts_AB),
// where the source regs are a full MMA-loop old (latency covered).
// Single __syncthreads per k-chunk:
//   iter i: sts(chunk i+1 -> buf (i+1)&1); ldg(chunk i+2); mma(buf i&1); sync
// CTA: 64(M) x 64(N), 4 warps of 32x32. Grid (32, 4, 2), split-K 2.
// ---------------------------------------------------------------------------
#define A_STAGE_B 8192
#define B_STAGE_B 8192

__global__ void __launch_bounds__(128, 2)
gemm_kernel(const float* __restrict__ x32, const float* __restrict__ q,
            const float* __restrict__ bias, const float* __restrict__ W32) {
    __shared__ __align__(1024) char smemA[2 * A_STAGE_B];
    __shared__ __align__(1024) char smemB[2 * B_STAGE_B];
    const uint32_t sbA = smem_u32(smemA);
    const uint32_t sbB = smem_u32(smemB);

    const int tid  = threadIdx.x;
    const int lane = tid & 31;
    const int wid  = tid >> 5;            // 0..3
    const int wy   = wid >> 1;            // warp m index (0/1)
    const int wx   = wid & 1;             // warp n index (0/1)
    const int gq   = lane >> 2;           // group id 0..7
    const int tq   = lane & 3;            // quad thread 0..3

    const int n0 = blockIdx.x * 64;       // 0..2047
    const int m0 = blockIdx.y * 64;       // 0..255
    const int z  = blockIdx.z;            // split-K half
    const int c0 = z * 8;

    // RAW fp32 staging (64 regs); conversion deferred to STS.
    float4 areg[4][2], breg[4][2];
    auto ldg_AB = [&](int c) {
        const int koff = c * 64;
        #pragma unroll
        for (int s = 0; s < 4; s++) {
            int u = tid + 128 * s;
            int r = u >> 3, j = u & 7;
            const float4* sa = reinterpret_cast<const float4*>(
                x32 + (m0 + r) * 1024 + koff + j * 8);
            const float4* sb = reinterpret_cast<const float4*>(
                W32 + (n0 + r) * 1024 + koff + j * 8);
            areg[s][0] = sa[0];
            areg[s][1] = sa[1];
            breg[s][0] = sb[0];
            breg[s][1] = sb[1];
        }
    };

    auto sts_AB = [&](int buf) {
        const uint32_t baseA = sbA + buf * A_STAGE_B;
        const uint32_t baseB = sbB + buf * B_STAGE_B;
        #pragma unroll
        for (int s = 0; s < 4; s++) {
            int u = tid + 128 * s;
            int r = u >> 3, j = u & 7;
            uint32_t swz = (uint32_t)((j ^ (r & 7)) << 4);
            sts128(baseA + r * 128 + swz, pack_hi8(areg[s][0], areg[s][1]));
            sts128(baseB + r * 128 + swz, pack_hi8(breg[s][0], breg[s][1]));
        }
    };

    float acc[2][4][4];
    #pragma unroll
    for (int mi = 0; mi < 2; mi++)
        #pragma unroll
        for (int nj = 0; nj < 4; nj++)
            #pragma unroll
            for (int e = 0; e < 4; e++)
                acc[mi][nj][e] = 0.0f;

    // Prologue: chunk0 -> smem buf0; chunk1 -> regs; one sync.
    ldg_AB(c0 + 0);
    sts_AB(0);
    ldg_AB(c0 + 1);
    __syncthreads();

    const int lrow = lane & 15;
    const int lcb  = lane >> 4;

    for (int i = 0; i < 8; i++) {
        const int buf = i & 1;

        if (i + 1 < 8) sts_AB((i + 1) & 1);   // pack + store chunk i+1
        if (i + 2 < 8) ldg_AB(c0 + i + 2);    // raw prefetch chunk i+2

        const uint32_t sa = sbA + buf * A_STAGE_B;
        const uint32_t sB = sbB + buf * B_STAGE_B;

        #pragma unroll
        for (int ks = 0; ks < 4; ks++) {
            const int j = ks * 2 + lcb;
            uint32_t a[2][4], b[2][4];
            #pragma unroll
            for (int mi = 0; mi < 2; mi++) {
                int r = wy * 32 + mi * 16 + lrow;
                ldsm_x4(a[mi], sa + r * 128 + ((j ^ (r & 7)) << 4));
            }
            #pragma unroll
            for (int nb = 0; nb < 2; nb++) {
                int r = wx * 32 + nb * 16 + lrow;
                ldsm_x4(b[nb], sB + r * 128 + ((j ^ (r & 7)) << 4));
            }
            #pragma unroll
            for (int mi = 0; mi < 2; mi++)
                #pragma unroll
                for (int nj = 0; nj < 4; nj++) {
                    const int nb = nj >> 1, sub = nj & 1;
                    mma16816(acc[mi][nj], a[mi], b[nb][sub], b[nb][sub + 2]);
                }
        }
        __syncthreads();   // sts(i+1) visible; read-buf swap is now safe
    }

    // ------------------------------------------------------------------
    // Fused epilogue. acc element (mi, nj, e):
    //   row = m0 + wy*32 + mi*16 + gq + (e>=2 ? 8 : 0)
    //   col = n0 + wx*32 + nj*8  + 2*tq + (e&1)
    // Bias added only by the z==0 half.
    // ------------------------------------------------------------------
    float2 bb[4];
    #pragma unroll
    for (int nj = 0; nj < 4; nj++) {
        if (z == 0) {
            const int col = n0 + wx * 32 + nj * 8 + 2 * tq;
            bb[nj] = *reinterpret_cast<const float2*>(bias + col);
        } else {
            bb[nj].x = 0.0f; bb[nj].y = 0.0f;
        }
    }

    if (n0 < 1024) {
        float part[4];
        #pragma unroll
        for (int mi = 0; mi < 2; mi++)
            #pragma unroll
            for (int rh = 0; rh < 2; rh++) {
                const int row = m0 + wy * 32 + mi * 16 + rh * 8 + gq;
                float s = 0.0f;
                #pragma unroll
                for (int nj = 0; nj < 4; nj++) {
                    const int col = n0 + wx * 32 + nj * 8 + 2 * tq;
                    float2 qq = *reinterpret_cast<const float2*>(q + row * 1024 + col);
                    s += (acc[mi][nj][rh * 2 + 0] + bb[nj].x) * qq.x;
                    s += (acc[mi][nj][rh * 2 + 1] + bb[nj].y) * qq.y;
                }
                part[mi * 2 + rh] = s;
            }
        #pragma unroll
        for (int sl = 0; sl < 4; sl++) {
            part[sl] += __shfl_xor_sync(0xFFFFFFFFu, part[sl], 1);
            part[sl] += __shfl_xor_sync(0xFFFFFFFFu, part[sl], 2);
        }
        if (tq == 0) {
            const int slot = z * 32 + blockIdx.x * 2 + wx;   // 0..63
            #pragma unroll
            for (int sl = 0; sl < 4; sl++) {
                const int row = m0 + wy * 32 + (sl >> 1) * 16 + (sl & 1) * 8 + gq;
                g_sp[row * 64 + slot] = part[sl];
            }
        }
    } else {
        float* vbase = g_vp + z * 256 * 1024;
        #pragma unroll
        for (int mi = 0; mi < 2; mi++)
            #pragma unroll
            for (int rh = 0; rh < 2; rh++) {
                const int row = m0 + wy * 32 + mi * 16 + rh * 8 + gq;
                #pragma unroll
                for (int nj = 0; nj < 4; nj++) {
                    const int col = (n0 - 1024) + wx * 32 + nj * 8 + 2 * tq;
                    float2 o;
                    o.x = acc[mi][nj][rh * 2 + 0] + bb[nj].x;
                    o.y = acc[mi][nj][rh * 2 + 1] + bb[nj].y;
                    *reinterpret_cast<float2*>(vbase + row * 1024 + col) = o;
                }
            }
    }
}

// ---------------------------------------------------------------------------
// Scale: out[b,:] = (v0[b,:]+v1[b,:]) * sum(g_sp[b][0..63])
// ---------------------------------------------------------------------------
__global__ __launch_bounds__(256) void scale_kernel(float* __restrict__ out) {
    const int b = blockIdx.x;
    const int t = threadIdx.x;
    const int w = t >> 5, l = t & 31;

    __shared__ float red[2];
    __shared__ float s_tot;
    float p = (t < 64) ? g_sp[b * 64 + t] : 0.0f;
    #pragma unroll
    for (int off = 16; off > 0; off >>= 1)
        p += __shfl_xor_sync(0xFFFFFFFFu, p, off);
    if (w < 2 && l == 0) red[w] = p;
    __syncthreads();
    if (t == 0) s_tot = red[0] + red[1];
    __syncthreads();
    const float s = s_tot;

    float4 v0 = reinterpret_cast<const float4*>(g_vp + b * 1024)[t];
    float4 v1 = reinterpret_cast<const float4*>(g_vp + 256 * 1024 + b * 1024)[t];
    float4 o;
    o.x = (v0.x + v1.x) * s;
    o.y = (v0.y + v1.y) * s;
    o.z = (v0.z + v1.z) * s;
    o.w = (v0.w + v1.w) * s;
    reinterpret_cast<float4*>(out + b * 1024)[t] = o;
}

// ---------------------------------------------------------------------------
extern "C" void kernel_launch(void* const* d_in, const int* in_sizes, int n_in,
                              void* d_out, int out_size) {
    const float* x  = (const float*)d_in[0];   // 256x1024
    const float* q  = (const float*)d_in[1];   // 256x1024
    const float* W  = (const float*)d_in[2];   // 2048x1024
    const float* bs = (const float*)d_in[3];   // 2048
    float* out = (float*)d_out;                // 256x1024

    gemm_kernel<<<dim3(32, 4, 2), 128>>>(x, q, bs, W);
    scale_kernel<<<256, 256>>>(out);
}